// round 2
// baseline (speedup 1.0000x reference)
#include <cuda_runtime.h>

#define NL 4
#define NNODE 50000
#define NEDGE 800000
#define FDIM 256

// ---------------- scratch (static device globals; no allocation allowed) ----
__device__ float    g_etmp[(size_t)NEDGE * FDIM];       // e_tmp  [E,F]
__device__ float    g_hw[(size_t)5 * NNODE * FDIM];     // hWs,hWd,hWf,hWb,h_tmp
__device__ float    g_logf[NEDGE];
__device__ float    g_logb[NEDGE];
__device__ float    g_alf[NEDGE];
__device__ float    g_alb[NEDGE];
__device__ unsigned g_mf[NNODE];
__device__ unsigned g_mb[NNODE];
__device__ float    g_df[NNODE];
__device__ float    g_db[NNODE];
__device__ float    g_sum[FDIM], g_ssq[FDIM], g_mean[FDIM], g_rstd[FDIM];

// ---------------- order-preserving float<->uint for atomic max ---------------
__device__ __forceinline__ unsigned fflip(float f) {
    unsigned b = __float_as_uint(f);
    return (b & 0x80000000u) ? ~b : (b | 0x80000000u);
}
__device__ __forceinline__ float funflip(unsigned u) {
    return (u & 0x80000000u) ? __uint_as_float(u & 0x7FFFFFFFu)
                             : __uint_as_float(~u);
}

// ---------------- SGEMM: C[M,256] = A[M,256] @ W[256,256] (+ edge gathers) ---
// Tile 128x64, BK=16, 256 threads, 8x4 per thread.
template <bool EDGE>
__global__ __launch_bounds__(256)
void sgemm(const float* __restrict__ A, const float* __restrict__ W,
           float* __restrict__ C, int M,
           const float* __restrict__ G0, const float* __restrict__ G1,
           const int* __restrict__ src, const int* __restrict__ dst)
{
    __shared__ __align__(16) float As[16][128];
    __shared__ __align__(16) float Bs[16][64];

    const int tid = threadIdx.x;
    const int bm  = blockIdx.x * 128;
    const int bn  = blockIdx.y * 64;
    const int tx  = tid & 15;   // 0..15 -> 4 cols each
    const int ty  = tid >> 4;   // 0..15 -> 8 rows each

    float acc[8][4];
#pragma unroll
    for (int i = 0; i < 8; i++)
#pragma unroll
        for (int j = 0; j < 4; j++) acc[i][j] = 0.f;

    for (int k0 = 0; k0 < 256; k0 += 16) {
        // load A tile (128x16), 2 float4 per thread, store transposed
#pragma unroll
        for (int it = 0; it < 2; it++) {
            int slot = tid + it * 256;       // 0..511
            int row  = slot >> 2;            // 0..127
            int c4   = slot & 3;             // 0..3
            int grow = bm + row;
            float4 v = make_float4(0.f, 0.f, 0.f, 0.f);
            if (grow < M)
                v = *(const float4*)(A + (size_t)grow * 256 + k0 + c4 * 4);
            As[c4 * 4 + 0][row] = v.x;
            As[c4 * 4 + 1][row] = v.y;
            As[c4 * 4 + 2][row] = v.z;
            As[c4 * 4 + 3][row] = v.w;
        }
        // load B tile (16x64), 1 float4 per thread
        {
            int row = tid >> 4;   // 0..15
            int c4  = tid & 15;   // 0..15
            float4 v = *(const float4*)(W + (size_t)(k0 + row) * 256 + bn + c4 * 4);
            *(float4*)(&Bs[row][c4 * 4]) = v;
        }
        __syncthreads();

#pragma unroll
        for (int k = 0; k < 16; k++) {
            float a[8], b[4];
            *(float4*)(a)     = *(const float4*)(&As[k][ty * 8]);
            *(float4*)(a + 4) = *(const float4*)(&As[k][ty * 8 + 4]);
            *(float4*)(b)     = *(const float4*)(&Bs[k][tx * 4]);
#pragma unroll
            for (int i = 0; i < 8; i++)
#pragma unroll
                for (int j = 0; j < 4; j++)
                    acc[i][j] = fmaf(a[i], b[j], acc[i][j]);
        }
        __syncthreads();
    }

    const int col = bn + tx * 4;
#pragma unroll
    for (int i = 0; i < 8; i++) {
        int row = bm + ty * 8 + i;
        if (row >= M) break;
        float4 o = make_float4(acc[i][0], acc[i][1], acc[i][2], acc[i][3]);
        if (EDGE) {
            int s = src[row], d = dst[row];
            float4 gs = *(const float4*)(G0 + (size_t)s * 256 + col);
            float4 gd = *(const float4*)(G1 + (size_t)d * 256 + col);
            o.x += gs.x + gd.x; o.y += gs.y + gd.y;
            o.z += gs.z + gd.z; o.w += gs.w + gd.w;
        }
        *(float4*)(C + (size_t)row * 256 + col) = o;
    }
}

// ---------------- BN column statistics ---------------------------------------
__global__ void k_zero_stats(float* __restrict__ sum, float* __restrict__ ssq) {
    int c = threadIdx.x;
    sum[c] = 0.f;
    ssq[c] = 0.f;
}

__global__ void k_colstats(const float* __restrict__ X, int M,
                           float* __restrict__ sum, float* __restrict__ ssq) {
    int c = threadIdx.x;  // 256 threads = 256 columns
    long chunk = ((long)M + gridDim.x - 1) / gridDim.x;
    long r0 = (long)blockIdx.x * chunk;
    long r1 = r0 + chunk;
    if (r1 > M) r1 = M;
    float s = 0.f, q = 0.f;
    long r = r0;
    for (; r + 4 <= r1; r += 4) {
        float v0 = X[(r + 0) * FDIM + c];
        float v1 = X[(r + 1) * FDIM + c];
        float v2 = X[(r + 2) * FDIM + c];
        float v3 = X[(r + 3) * FDIM + c];
        s += (v0 + v1) + (v2 + v3);
        q += (v0 * v0 + v1 * v1) + (v2 * v2 + v3 * v3);
    }
    for (; r < r1; r++) { float v = X[r * FDIM + c]; s += v; q += v * v; }
    atomicAdd(&sum[c], s);
    atomicAdd(&ssq[c], q);
}

__global__ void k_bnfin(const float* __restrict__ sum, const float* __restrict__ ssq,
                        int M, float* __restrict__ mean, float* __restrict__ rstd) {
    int c = threadIdx.x;
    float mu  = sum[c] / (float)M;
    float var = ssq[c] / (float)M - mu * mu;
    mean[c] = mu;
    rstd[c] = rsqrtf(var + 1e-5f);
}

// ---------------- logits: leaky_relu(e_tmp @ a) (warp per row) ---------------
__global__ void k_logits(const float* __restrict__ X,
                         const float* __restrict__ af, const float* __restrict__ ab,
                         float* __restrict__ lf, float* __restrict__ lb) {
    long gtid = (long)blockIdx.x * blockDim.x + threadIdx.x;
    long wrow = gtid >> 5;
    int lane  = (int)(gtid & 31);
    if (wrow >= NEDGE) return;
    const float4* row = (const float4*)(X + wrow * FDIM);
    const float4* f4  = (const float4*)af;
    const float4* b4  = (const float4*)ab;
    float sf = 0.f, sb = 0.f;
#pragma unroll
    for (int i = 0; i < 2; i++) {
        int idx = lane + i * 32;  // 0..63 float4s
        float4 v = row[idx];
        float4 fa = f4[idx];
        float4 ba = b4[idx];
        sf += v.x * fa.x + v.y * fa.y + v.z * fa.z + v.w * fa.w;
        sb += v.x * ba.x + v.y * ba.y + v.z * ba.z + v.w * ba.w;
    }
#pragma unroll
    for (int o = 16; o > 0; o >>= 1) {
        sf += __shfl_down_sync(0xffffffffu, sf, o);
        sb += __shfl_down_sync(0xffffffffu, sb, o);
    }
    if (lane == 0) {
        lf[wrow] = sf > 0.f ? sf : 0.2f * sf;
        lb[wrow] = sb > 0.f ? sb : 0.2f * sb;
    }
}

// ---------------- residual + BN + relu (elementwise, float4) -----------------
__global__ void k_bnres(float4* __restrict__ out, const float4* __restrict__ in,
                        const float4* __restrict__ tmp,
                        const float4* __restrict__ mean, const float4* __restrict__ rstd,
                        const float4* __restrict__ gam, const float4* __restrict__ bet,
                        long n4) {
    long i = (long)blockIdx.x * blockDim.x + threadIdx.x;
    if (i >= n4) return;
    int c = (int)(i & 63);
    float4 t = tmp[i], v = in[i];
    float4 m = mean[c], r = rstd[c], g = gam[c], b = bet[c];
    float x;
    x = (t.x - m.x) * r.x * g.x + b.x; v.x += x > 0.f ? x : 0.f;
    x = (t.y - m.y) * r.y * g.y + b.y; v.y += x > 0.f ? x : 0.f;
    x = (t.z - m.z) * r.z * g.z + b.z; v.z += x > 0.f ? x : 0.f;
    x = (t.w - m.w) * r.w * g.w + b.w; v.w += x > 0.f ? x : 0.f;
    out[i] = v;
}

// ---------------- segment softmax pieces -------------------------------------
__global__ void k_seg_init(unsigned* __restrict__ mf, unsigned* __restrict__ mb,
                           float* __restrict__ df, float* __restrict__ db) {
    int i = blockIdx.x * blockDim.x + threadIdx.x;
    if (i < NNODE) { mf[i] = 0u; mb[i] = 0u; df[i] = 0.f; db[i] = 0.f; }
}

__global__ void k_segmax(const float* __restrict__ lf, const float* __restrict__ lb,
                         const int* __restrict__ src, const int* __restrict__ dst,
                         unsigned* __restrict__ mf, unsigned* __restrict__ mb) {
    int i = blockIdx.x * blockDim.x + threadIdx.x;
    if (i >= NEDGE) return;
    atomicMax(&mf[dst[i]], fflip(lf[i]));
    atomicMax(&mb[src[i]], fflip(lb[i]));
}

__global__ void k_segden(const float* __restrict__ lf, const float* __restrict__ lb,
                         const int* __restrict__ src, const int* __restrict__ dst,
                         const unsigned* __restrict__ mf, const unsigned* __restrict__ mb,
                         float* __restrict__ df, float* __restrict__ db,
                         float* __restrict__ alf, float* __restrict__ alb) {
    int i = blockIdx.x * blockDim.x + threadIdx.x;
    if (i >= NEDGE) return;
    int d = dst[i], s = src[i];
    float ef = expf(lf[i] - funflip(mf[d]));
    float eb = expf(lb[i] - funflip(mb[s]));
    alf[i] = ef;
    alb[i] = eb;
    atomicAdd(&df[d], ef);
    atomicAdd(&db[s], eb);
}

__global__ void k_segnorm(float* __restrict__ alf, float* __restrict__ alb,
                          const int* __restrict__ src, const int* __restrict__ dst,
                          const float* __restrict__ df, const float* __restrict__ db) {
    int i = blockIdx.x * blockDim.x + threadIdx.x;
    if (i >= NEDGE) return;
    alf[i] = alf[i] / (df[dst[i]] + 1e-9f);
    alb[i] = alb[i] / (db[src[i]] + 1e-9f);
}

// ---------------- attention aggregation (scatter, block per edge) ------------
__global__ __launch_bounds__(256)
void k_scatter(const int* __restrict__ src, const int* __restrict__ dst,
               const float* __restrict__ alf, const float* __restrict__ alb,
               const float* __restrict__ hwf, const float* __restrict__ hwb,
               float* __restrict__ htmp) {
    int e = blockIdx.x;
    int t = threadIdx.x;
    int s = src[e], d = dst[e];
    float af = alf[e], ab = alb[e];
    atomicAdd(&htmp[(size_t)d * FDIM + t], af * hwf[(size_t)s * FDIM + t]);
    atomicAdd(&htmp[(size_t)s * FDIM + t], ab * hwb[(size_t)d * FDIM + t]);
}

// ---------------- launcher ---------------------------------------------------
extern "C" void kernel_launch(void* const* d_in, const int* in_sizes, int n_in,
                              void* d_out, int out_size) {
    const float* in_h   = (const float*)d_in[0];
    const float* in_e   = (const float*)d_in[1];
    const int*   src    = (const int*)d_in[2];
    const int*   dst    = (const int*)d_in[3];
    const float* We     = (const float*)d_in[4];
    const float* Ws     = (const float*)d_in[5];
    const float* Wd     = (const float*)d_in[6];
    const float* Wself  = (const float*)d_in[7];
    const float* Wf     = (const float*)d_in[8];
    const float* Wb     = (const float*)d_in[9];
    const float* att_f  = (const float*)d_in[10];
    const float* att_b  = (const float*)d_in[11];
    const float* ge     = (const float*)d_in[12];
    const float* be     = (const float*)d_in[13];
    const float* gh     = (const float*)d_in[14];
    const float* bh     = (const float*)d_in[15];

    float* h_out = (float*)d_out;                           // [N,F]
    float* e_out = (float*)d_out + (size_t)NNODE * FDIM;    // [E,F]

    float *etmp, *hw, *logf, *logb, *alf, *alb, *df, *db, *sum, *ssq, *mean, *rstd;
    unsigned *mf, *mb;
    cudaGetSymbolAddress((void**)&etmp, g_etmp);
    cudaGetSymbolAddress((void**)&hw,   g_hw);
    cudaGetSymbolAddress((void**)&logf, g_logf);
    cudaGetSymbolAddress((void**)&logb, g_logb);
    cudaGetSymbolAddress((void**)&alf,  g_alf);
    cudaGetSymbolAddress((void**)&alb,  g_alb);
    cudaGetSymbolAddress((void**)&mf,   g_mf);
    cudaGetSymbolAddress((void**)&mb,   g_mb);
    cudaGetSymbolAddress((void**)&df,   g_df);
    cudaGetSymbolAddress((void**)&db,   g_db);
    cudaGetSymbolAddress((void**)&sum,  g_sum);
    cudaGetSymbolAddress((void**)&ssq,  g_ssq);
    cudaGetSymbolAddress((void**)&mean, g_mean);
    cudaGetSymbolAddress((void**)&rstd, g_rstd);

    const size_t NF = (size_t)NNODE * FDIM;
    float* hws  = hw + 0 * NF;
    float* hwd  = hw + 1 * NF;
    float* hwf  = hw + 2 * NF;
    float* hwb  = hw + 3 * NF;
    float* htmp = hw + 4 * NF;

    dim3 gN((NNODE + 127) / 128, 4);
    dim3 gE(NEDGE / 128, 4);

    for (int l = 0; l < NL; l++) {
        const float* h_in = (l == 0) ? in_h : h_out;
        const float* e_in = (l == 0) ? in_e : e_out;
        size_t WO = (size_t)l * FDIM * FDIM;
        size_t VO = (size_t)l * FDIM;

        // node projections: hWs, hWd, hWf, hWb, h_tmp = h@Wself
        sgemm<false><<<gN, 256>>>(h_in, Ws + WO, hws, NNODE, nullptr, nullptr, nullptr, nullptr);
        sgemm<false><<<gN, 256>>>(h_in, Wd + WO, hwd, NNODE, nullptr, nullptr, nullptr, nullptr);
        sgemm<false><<<gN, 256>>>(h_in, Wf + WO, hwf, NNODE, nullptr, nullptr, nullptr, nullptr);
        sgemm<false><<<gN, 256>>>(h_in, Wb + WO, hwb, NNODE, nullptr, nullptr, nullptr, nullptr);
        sgemm<false><<<gN, 256>>>(h_in, Wself + WO, htmp, NNODE, nullptr, nullptr, nullptr, nullptr);

        // e_tmp = e@We + hWs[src] + hWd[dst]
        sgemm<true><<<gE, 256>>>(e_in, We + WO, etmp, NEDGE, hws, hwd, src, dst);

        // BN stats for e_tmp
        k_zero_stats<<<1, 256>>>(sum, ssq);
        k_colstats<<<1024, 256>>>(etmp, NEDGE, sum, ssq);
        k_bnfin<<<1, 256>>>(sum, ssq, NEDGE, mean, rstd);

        // attention logits from raw e_tmp
        k_logits<<<(int)(((long)NEDGE * 32 + 255) / 256), 256>>>(etmp, att_f + VO, att_b + VO, logf, logb);

        // e_new = e + relu(bn(e_tmp))
        k_bnres<<<(int)(((long)NEDGE * 64 + 255) / 256), 256>>>(
            (float4*)e_out, (const float4*)e_in, (const float4*)etmp,
            (const float4*)mean, (const float4*)rstd,
            (const float4*)(ge + VO), (const float4*)(be + VO), (long)NEDGE * 64);

        // segment softmax (forward into dst, backward into src)
        k_seg_init<<<(NNODE + 255) / 256, 256>>>(mf, mb, df, db);
        k_segmax<<<(NEDGE + 255) / 256, 256>>>(logf, logb, src, dst, mf, mb);
        k_segden<<<(NEDGE + 255) / 256, 256>>>(logf, logb, src, dst, mf, mb, df, db, alf, alb);
        k_segnorm<<<(NEDGE + 255) / 256, 256>>>(alf, alb, src, dst, df, db);

        // h_tmp += agg_f + agg_b
        k_scatter<<<NEDGE, 256>>>(src, dst, alf, alb, hwf, hwb, htmp);

        // BN over h_tmp, h_new = h + relu(bn(h_tmp))
        k_zero_stats<<<1, 256>>>(sum, ssq);
        k_colstats<<<256, 256>>>(htmp, NNODE, sum, ssq);
        k_bnfin<<<1, 256>>>(sum, ssq, NNODE, mean, rstd);
        k_bnres<<<(int)(((long)NNODE * 64 + 255) / 256), 256>>>(
            (float4*)h_out, (const float4*)h_in, (const float4*)htmp,
            (const float4*)mean, (const float4*)rstd,
            (const float4*)(gh + VO), (const float4*)(bh + VO), (long)NNODE * 64);
    }
}

// round 5
// speedup vs baseline: 2.0770x; 2.0770x over previous
#include <cuda_runtime.h>

#define NL 4
#define NNODE 50000
#define NEDGE 800000
#define FDIM 256

// ---------------- scratch (static device globals; no allocation allowed) ----
__device__ float    g_etmp[(size_t)NEDGE * FDIM];       // e_tmp  [E,F]
__device__ float    g_hw[(size_t)5 * NNODE * FDIM];     // hWs,hWd,hWf,hWb,h_tmp
__device__ float    g_logf[NEDGE];
__device__ float    g_logb[NEDGE];
__device__ float    g_alf[NEDGE];
__device__ float    g_alb[NEDGE];
__device__ unsigned g_mf[NNODE];
__device__ unsigned g_mb[NNODE];
__device__ float    g_df[NNODE];
__device__ float    g_db[NNODE];
__device__ float    g_sum[FDIM], g_ssq[FDIM], g_mean[FDIM], g_rstd[FDIM];

// ---------------- helpers ----------------------------------------------------
__device__ __forceinline__ unsigned fflip(float f) {
    unsigned b = __float_as_uint(f);
    return (b & 0x80000000u) ? ~b : (b | 0x80000000u);
}
__device__ __forceinline__ float funflip(unsigned u) {
    return (u & 0x80000000u) ? __uint_as_float(u & 0x7FFFFFFFu)
                             : __uint_as_float(~u);
}
__device__ __forceinline__ float ftf32(float x) {
    asm("cvt.rna.tf32.f32 %0, %0;" : "+f"(x));
    return x;
}
__device__ __forceinline__ void mma8(float* c, const unsigned* a, const unsigned* b) {
    asm volatile(
        "mma.sync.aligned.m16n8k8.row.col.f32.tf32.tf32.f32 "
        "{%0,%1,%2,%3}, {%4,%5,%6,%7}, {%8,%9}, {%0,%1,%2,%3};"
        : "+f"(c[0]), "+f"(c[1]), "+f"(c[2]), "+f"(c[3])
        : "r"(a[0]), "r"(a[1]), "r"(a[2]), "r"(a[3]), "r"(b[0]), "r"(b[1]));
}

// ---------------- TF32 tensor-core GEMM --------------------------------------
// C[M,256] = A[M,256] @ W[256,256]  (+ optional edge gathers in epilogue)
// Block tile 128x128, BK=16, 256 threads = 8 warps (4 along M x 2 along N),
// warp tile 32x64, double-buffered SMEM.
#define BM 128
#define BN 128
#define BK 16
#define APAD 20    // As row stride (floats): conflict-free frag loads
#define BPAD 136   // Bs row stride (floats): conflict-free frag loads

template <bool EDGE>
__global__ __launch_bounds__(256)
void tgemm(const float* __restrict__ A, const float* __restrict__ W,
           float* __restrict__ C, int M,
           const float* __restrict__ G0, const float* __restrict__ G1,
           const int* __restrict__ src, const int* __restrict__ dst)
{
    __shared__ __align__(16) float As[2][BM][APAD];
    __shared__ __align__(16) float Bs[2][BK][BPAD];

    const int tid  = threadIdx.x;
    const int warp = tid >> 5;
    const int lane = tid & 31;
    const int wm   = warp & 3;    // m offset = wm*32
    const int wn   = warp >> 2;   // n offset = wn*64
    const int bm   = blockIdx.x * BM;
    const int bn   = blockIdx.y * BN;
    const int g    = lane >> 2;   // groupID 0..7
    const int tg   = lane & 3;    // thread-in-group 0..3

    // global load mapping
    const int ar0 = tid >> 2;          // A rows: ar0 and ar0+64
    const int ac  = (tid & 3) * 4;     // A col quad
    const int br0 = tid >> 5;          // B rows: br0 and br0+8
    const int bc0 = (tid & 31) * 4;    // B col quad

    float acc[2][8][4];
#pragma unroll
    for (int i = 0; i < 2; i++)
#pragma unroll
        for (int j = 0; j < 8; j++)
#pragma unroll
            for (int q = 0; q < 4; q++) acc[i][j][q] = 0.f;

    float4 av[2], bv[2];

    auto gload = [&](int k0) {
        const float4 z = make_float4(0.f, 0.f, 0.f, 0.f);
        int r0 = bm + ar0, r1 = bm + ar0 + 64;
        av[0] = (r0 < M) ? *(const float4*)(A + (size_t)r0 * 256 + k0 + ac) : z;
        av[1] = (r1 < M) ? *(const float4*)(A + (size_t)r1 * 256 + k0 + ac) : z;
        bv[0] = *(const float4*)(W + (size_t)(k0 + br0) * 256 + bn + bc0);
        bv[1] = *(const float4*)(W + (size_t)(k0 + br0 + 8) * 256 + bn + bc0);
    };
    auto sstore = [&](int s) {
        float4 v;
        v = av[0]; v.x = ftf32(v.x); v.y = ftf32(v.y); v.z = ftf32(v.z); v.w = ftf32(v.w);
        *(float4*)(&As[s][ar0][ac]) = v;
        v = av[1]; v.x = ftf32(v.x); v.y = ftf32(v.y); v.z = ftf32(v.z); v.w = ftf32(v.w);
        *(float4*)(&As[s][ar0 + 64][ac]) = v;
        v = bv[0]; v.x = ftf32(v.x); v.y = ftf32(v.y); v.z = ftf32(v.z); v.w = ftf32(v.w);
        *(float4*)(&Bs[s][br0][bc0]) = v;
        v = bv[1]; v.x = ftf32(v.x); v.y = ftf32(v.y); v.z = ftf32(v.z); v.w = ftf32(v.w);
        *(float4*)(&Bs[s][br0 + 8][bc0]) = v;
    };

    gload(0);
    sstore(0);
    __syncthreads();

#pragma unroll 2
    for (int kt = 0; kt < 16; kt++) {
        const int cur = kt & 1;
        if (kt < 15) gload((kt + 1) * BK);

#pragma unroll
        for (int ks = 0; ks < 2; ks++) {
            const int k = ks * 8;
            unsigned af[2][4];
#pragma unroll
            for (int mt = 0; mt < 2; mt++) {
                const int rb = wm * 32 + mt * 16;
                af[mt][0] = __float_as_uint(As[cur][rb + g][k + tg]);
                af[mt][1] = __float_as_uint(As[cur][rb + g + 8][k + tg]);
                af[mt][2] = __float_as_uint(As[cur][rb + g][k + tg + 4]);
                af[mt][3] = __float_as_uint(As[cur][rb + g + 8][k + tg + 4]);
            }
            unsigned bf[8][2];
#pragma unroll
            for (int nt = 0; nt < 8; nt++) {
                const int n = wn * 64 + nt * 8 + g;
                bf[nt][0] = __float_as_uint(Bs[cur][k + tg][n]);
                bf[nt][1] = __float_as_uint(Bs[cur][k + tg + 4][n]);
            }
#pragma unroll
            for (int mt = 0; mt < 2; mt++)
#pragma unroll
                for (int nt = 0; nt < 8; nt++)
                    mma8(acc[mt][nt], af[mt], bf[nt]);
        }

        __syncthreads();
        if (kt < 15) {
            sstore((kt + 1) & 1);
            __syncthreads();
        }
    }

    // epilogue
#pragma unroll
    for (int mt = 0; mt < 2; mt++) {
#pragma unroll
        for (int rr = 0; rr < 2; rr++) {
            const int r = bm + wm * 32 + mt * 16 + rr * 8 + g;
            if (r < M) {
                int s = 0, d = 0;
                if (EDGE) { s = src[r]; d = dst[r]; }
#pragma unroll
                for (int nt = 0; nt < 8; nt++) {
                    const int col = bn + wn * 64 + nt * 8 + tg * 2;
                    float2 o = make_float2(acc[mt][nt][rr * 2], acc[mt][nt][rr * 2 + 1]);
                    if (EDGE) {
                        float2 gs = *(const float2*)(G0 + (size_t)s * 256 + col);
                        float2 gd = *(const float2*)(G1 + (size_t)d * 256 + col);
                        o.x += gs.x + gd.x;
                        o.y += gs.y + gd.y;
                    }
                    *(float2*)(C + (size_t)r * 256 + col) = o;
                }
            }
        }
    }
}

// ---------------- BN column statistics ---------------------------------------
__global__ void k_zero_stats(float* __restrict__ sum, float* __restrict__ ssq) {
    int c = threadIdx.x;
    sum[c] = 0.f;
    ssq[c] = 0.f;
}

__global__ void k_colstats(const float* __restrict__ X, int M,
                           float* __restrict__ sum, float* __restrict__ ssq) {
    int c = threadIdx.x;
    long chunk = ((long)M + gridDim.x - 1) / gridDim.x;
    long r0 = (long)blockIdx.x * chunk;
    long r1 = r0 + chunk;
    if (r1 > M) r1 = M;
    float s = 0.f, q = 0.f;
    long r = r0;
    for (; r + 4 <= r1; r += 4) {
        float v0 = X[(r + 0) * FDIM + c];
        float v1 = X[(r + 1) * FDIM + c];
        float v2 = X[(r + 2) * FDIM + c];
        float v3 = X[(r + 3) * FDIM + c];
        s += (v0 + v1) + (v2 + v3);
        q += (v0 * v0 + v1 * v1) + (v2 * v2 + v3 * v3);
    }
    for (; r < r1; r++) { float v = X[r * FDIM + c]; s += v; q += v * v; }
    atomicAdd(&sum[c], s);
    atomicAdd(&ssq[c], q);
}

__global__ void k_bnfin(const float* __restrict__ sum, const float* __restrict__ ssq,
                        int M, float* __restrict__ mean, float* __restrict__ rstd) {
    int c = threadIdx.x;
    float mu  = sum[c] / (float)M;
    float var = ssq[c] / (float)M - mu * mu;
    mean[c] = mu;
    rstd[c] = rsqrtf(var + 1e-5f);
}

// ---------------- logits: leaky_relu(e_tmp @ a) (warp per row) ---------------
__global__ void k_logits(const float* __restrict__ X,
                         const float* __restrict__ af, const float* __restrict__ ab,
                         float* __restrict__ lf, float* __restrict__ lb) {
    long gtid = (long)blockIdx.x * blockDim.x + threadIdx.x;
    long wrow = gtid >> 5;
    int lane  = (int)(gtid & 31);
    if (wrow >= NEDGE) return;
    const float4* row = (const float4*)(X + wrow * FDIM);
    const float4* f4  = (const float4*)af;
    const float4* b4  = (const float4*)ab;
    float sf = 0.f, sb = 0.f;
#pragma unroll
    for (int i = 0; i < 2; i++) {
        int idx = lane + i * 32;
        float4 v = row[idx];
        float4 fa = f4[idx];
        float4 ba = b4[idx];
        sf += v.x * fa.x + v.y * fa.y + v.z * fa.z + v.w * fa.w;
        sb += v.x * ba.x + v.y * ba.y + v.z * ba.z + v.w * ba.w;
    }
#pragma unroll
    for (int o = 16; o > 0; o >>= 1) {
        sf += __shfl_down_sync(0xffffffffu, sf, o);
        sb += __shfl_down_sync(0xffffffffu, sb, o);
    }
    if (lane == 0) {
        lf[wrow] = sf > 0.f ? sf : 0.2f * sf;
        lb[wrow] = sb > 0.f ? sb : 0.2f * sb;
    }
}

// ---------------- residual + BN + relu (elementwise, float4) -----------------
__global__ void k_bnres(float4* __restrict__ out, const float4* __restrict__ in,
                        const float4* __restrict__ tmp,
                        const float4* __restrict__ mean, const float4* __restrict__ rstd,
                        const float4* __restrict__ gam, const float4* __restrict__ bet,
                        long n4) {
    long i = (long)blockIdx.x * blockDim.x + threadIdx.x;
    if (i >= n4) return;
    int c = (int)(i & 63);
    float4 t = tmp[i], v = in[i];
    float4 m = mean[c], r = rstd[c], g = gam[c], b = bet[c];
    float x;
    x = (t.x - m.x) * r.x * g.x + b.x; v.x += x > 0.f ? x : 0.f;
    x = (t.y - m.y) * r.y * g.y + b.y; v.y += x > 0.f ? x : 0.f;
    x = (t.z - m.z) * r.z * g.z + b.z; v.z += x > 0.f ? x : 0.f;
    x = (t.w - m.w) * r.w * g.w + b.w; v.w += x > 0.f ? x : 0.f;
    out[i] = v;
}

// ---------------- segment softmax pieces -------------------------------------
__global__ void k_seg_init(unsigned* __restrict__ mf, unsigned* __restrict__ mb,
                           float* __restrict__ df, float* __restrict__ db) {
    int i = blockIdx.x * blockDim.x + threadIdx.x;
    if (i < NNODE) { mf[i] = 0u; mb[i] = 0u; df[i] = 0.f; db[i] = 0.f; }
}

__global__ void k_segmax(const float* __restrict__ lf, const float* __restrict__ lb,
                         const int* __restrict__ src, const int* __restrict__ dst,
                         unsigned* __restrict__ mf, unsigned* __restrict__ mb) {
    int i = blockIdx.x * blockDim.x + threadIdx.x;
    if (i >= NEDGE) return;
    atomicMax(&mf[dst[i]], fflip(lf[i]));
    atomicMax(&mb[src[i]], fflip(lb[i]));
}

__global__ void k_segden(const float* __restrict__ lf, const float* __restrict__ lb,
                         const int* __restrict__ src, const int* __restrict__ dst,
                         const unsigned* __restrict__ mf, const unsigned* __restrict__ mb,
                         float* __restrict__ df, float* __restrict__ db,
                         float* __restrict__ alf, float* __restrict__ alb) {
    int i = blockIdx.x * blockDim.x + threadIdx.x;
    if (i >= NEDGE) return;
    int d = dst[i], s = src[i];
    float ef = expf(lf[i] - funflip(mf[d]));
    float eb = expf(lb[i] - funflip(mb[s]));
    alf[i] = ef;
    alb[i] = eb;
    atomicAdd(&df[d], ef);
    atomicAdd(&db[s], eb);
}

__global__ void k_segnorm(float* __restrict__ alf, float* __restrict__ alb,
                          const int* __restrict__ src, const int* __restrict__ dst,
                          const float* __restrict__ df, const float* __restrict__ db) {
    int i = blockIdx.x * blockDim.x + threadIdx.x;
    if (i >= NEDGE) return;
    alf[i] = alf[i] / (df[dst[i]] + 1e-9f);
    alb[i] = alb[i] / (db[src[i]] + 1e-9f);
}

// ---------------- attention aggregation (scatter, red.v4) --------------------
__global__ __launch_bounds__(256)
void k_scatter(const int* __restrict__ src, const int* __restrict__ dst,
               const float* __restrict__ alf, const float* __restrict__ alb,
               const float* __restrict__ hwf, const float* __restrict__ hwb,
               float* __restrict__ htmp) {
    long gt = (long)blockIdx.x * blockDim.x + threadIdx.x;
    int e = (int)(gt >> 6);
    int q = (int)(gt & 63);      // quad index: 64 float4 = 256 floats
    if (e >= NEDGE) return;
    int s = __ldg(&src[e]), d = __ldg(&dst[e]);
    float af = __ldg(&alf[e]),  ab = __ldg(&alb[e]);
    float4 vf = *(const float4*)(hwf + (size_t)s * FDIM + q * 4);
    float4 vb = *(const float4*)(hwb + (size_t)d * FDIM + q * 4);
    float* pd = htmp + (size_t)d * FDIM + q * 4;
    float* ps = htmp + (size_t)s * FDIM + q * 4;
    asm volatile("red.global.add.v4.f32 [%0], {%1,%2,%3,%4};"
                 :: "l"(pd), "f"(af * vf.x), "f"(af * vf.y), "f"(af * vf.z), "f"(af * vf.w)
                 : "memory");
    asm volatile("red.global.add.v4.f32 [%0], {%1,%2,%3,%4};"
                 :: "l"(ps), "f"(ab * vb.x), "f"(ab * vb.y), "f"(ab * vb.z), "f"(ab * vb.w)
                 : "memory");
}

// ---------------- launcher ---------------------------------------------------
extern "C" void kernel_launch(void* const* d_in, const int* in_sizes, int n_in,
                              void* d_out, int out_size) {
    const float* in_h   = (const float*)d_in[0];
    const float* in_e   = (const float*)d_in[1];
    const int*   src    = (const int*)d_in[2];
    const int*   dst    = (const int*)d_in[3];
    const float* We     = (const float*)d_in[4];
    const float* Ws     = (const float*)d_in[5];
    const float* Wd     = (const float*)d_in[6];
    const float* Wself  = (const float*)d_in[7];
    const float* Wf     = (const float*)d_in[8];
    const float* Wb     = (const float*)d_in[9];
    const float* att_f  = (const float*)d_in[10];
    const float* att_b  = (const float*)d_in[11];
    const float* ge     = (const float*)d_in[12];
    const float* be     = (const float*)d_in[13];
    const float* gh     = (const float*)d_in[14];
    const float* bh     = (const float*)d_in[15];

    float* h_out = (float*)d_out;
    float* e_out = (float*)d_out + (size_t)NNODE * FDIM;

    float *etmp, *hw, *logf, *logb, *alf, *alb, *df, *db, *sum, *ssq, *mean, *rstd;
    unsigned *mf, *mb;
    cudaGetSymbolAddress((void**)&etmp, g_etmp);
    cudaGetSymbolAddress((void**)&hw,   g_hw);
    cudaGetSymbolAddress((void**)&logf, g_logf);
    cudaGetSymbolAddress((void**)&logb, g_logb);
    cudaGetSymbolAddress((void**)&alf,  g_alf);
    cudaGetSymbolAddress((void**)&alb,  g_alb);
    cudaGetSymbolAddress((void**)&mf,   g_mf);
    cudaGetSymbolAddress((void**)&mb,   g_mb);
    cudaGetSymbolAddress((void**)&df,   g_df);
    cudaGetSymbolAddress((void**)&db,   g_db);
    cudaGetSymbolAddress((void**)&sum,  g_sum);
    cudaGetSymbolAddress((void**)&ssq,  g_ssq);
    cudaGetSymbolAddress((void**)&mean, g_mean);
    cudaGetSymbolAddress((void**)&rstd, g_rstd);

    const size_t NF = (size_t)NNODE * FDIM;
    float* hws  = hw + 0 * NF;
    float* hwd  = hw + 1 * NF;
    float* hwf  = hw + 2 * NF;
    float* hwb  = hw + 3 * NF;
    float* htmp = hw + 4 * NF;

    dim3 gN((NNODE + BM - 1) / BM, 2);
    dim3 gE(NEDGE / BM, 2);

    for (int l = 0; l < NL; l++) {
        const float* h_in = (l == 0) ? in_h : h_out;
        const float* e_in = (l == 0) ? in_e : e_out;
        size_t WO = (size_t)l * FDIM * FDIM;
        size_t VO = (size_t)l * FDIM;

        tgemm<false><<<gN, 256>>>(h_in, Ws + WO, hws, NNODE, nullptr, nullptr, nullptr, nullptr);
        tgemm<false><<<gN, 256>>>(h_in, Wd + WO, hwd, NNODE, nullptr, nullptr, nullptr, nullptr);
        tgemm<false><<<gN, 256>>>(h_in, Wf + WO, hwf, NNODE, nullptr, nullptr, nullptr, nullptr);
        tgemm<false><<<gN, 256>>>(h_in, Wb + WO, hwb, NNODE, nullptr, nullptr, nullptr, nullptr);
        tgemm<false><<<gN, 256>>>(h_in, Wself + WO, htmp, NNODE, nullptr, nullptr, nullptr, nullptr);

        tgemm<true><<<gE, 256>>>(e_in, We + WO, etmp, NEDGE, hws, hwd, src, dst);

        k_zero_stats<<<1, 256>>>(sum, ssq);
        k_colstats<<<1024, 256>>>(etmp, NEDGE, sum, ssq);
        k_bnfin<<<1, 256>>>(sum, ssq, NEDGE, mean, rstd);

        k_logits<<<(int)(((long)NEDGE * 32 + 255) / 256), 256>>>(etmp, att_f + VO, att_b + VO, logf, logb);

        k_bnres<<<(int)(((long)NEDGE * 64 + 255) / 256), 256>>>(
            (float4*)e_out, (const float4*)e_in, (const float4*)etmp,
            (const float4*)mean, (const float4*)rstd,
            (const float4*)(ge + VO), (const float4*)(be + VO), (long)NEDGE * 64);

        k_seg_init<<<(NNODE + 255) / 256, 256>>>(mf, mb, df, db);
        k_segmax<<<(NEDGE + 255) / 256, 256>>>(logf, logb, src, dst, mf, mb);
        k_segden<<<(NEDGE + 255) / 256, 256>>>(logf, logb, src, dst, mf, mb, df, db, alf, alb);
        k_segnorm<<<(NEDGE + 255) / 256, 256>>>(alf, alb, src, dst, df, db);

        k_scatter<<<(int)(((long)NEDGE * 64 + 255) / 256), 256>>>(src, dst, alf, alb, hwf, hwb, htmp);

        k_zero_stats<<<1, 256>>>(sum, ssq);
        k_colstats<<<256, 256>>>(htmp, NNODE, sum, ssq);
        k_bnfin<<<1, 256>>>(sum, ssq, NNODE, mean, rstd);
        k_bnres<<<(int)(((long)NNODE * 64 + 255) / 256), 256>>>(
            (float4*)h_out, (const float4*)h_in, (const float4*)htmp,
            (const float4*)mean, (const float4*)rstd,
            (const float4*)(gh + VO), (const float4*)(bh + VO), (long)NNODE * 64);
    }
}

// round 7
// speedup vs baseline: 2.0804x; 1.0017x over previous
#include <cuda_runtime.h>

#define NL 4
#define NNODE 50000
#define NEDGE 800000
#define FDIM 256

// ---------------- scratch (static device globals; no allocation allowed) ----
__device__ float    g_etmp[(size_t)NEDGE * FDIM];       // e_tmp  [E,F]
__device__ float    g_hw[(size_t)5 * NNODE * FDIM];     // hWs,hWd,hWf,hWb,h_tmp
__device__ float    g_logf[NEDGE];
__device__ float    g_logb[NEDGE];
__device__ int      g_degf[NNODE], g_degb[NNODE];
__device__ int      g_rpf[NNODE + 1], g_rpb[NNODE + 1];
__device__ int      g_curf[NNODE], g_curb[NNODE];
__device__ int      g_eidf[NEDGE], g_eidb[NEDGE];
__device__ float    g_sum[FDIM], g_ssq[FDIM], g_mean[FDIM], g_rstd[FDIM];

// ---------------- helpers ----------------------------------------------------
__device__ __forceinline__ float ftf32(float x) {
    asm("cvt.rna.tf32.f32 %0, %0;" : "+f"(x));
    return x;
}
__device__ __forceinline__ void mma8(float* c, const unsigned* a, const unsigned* b) {
    asm volatile(
        "mma.sync.aligned.m16n8k8.row.col.f32.tf32.tf32.f32 "
        "{%0,%1,%2,%3}, {%4,%5,%6,%7}, {%8,%9}, {%0,%1,%2,%3};"
        : "+f"(c[0]), "+f"(c[1]), "+f"(c[2]), "+f"(c[3])
        : "r"(a[0]), "r"(a[1]), "r"(a[2]), "r"(a[3]), "r"(b[0]), "r"(b[1]));
}

// ---------------- TF32 tensor-core GEMM body ---------------------------------
#define BM 128
#define BN 128
#define BK 16
#define APAD 20
#define BPAD 136

template <bool EDGE>
__device__ __forceinline__ void gemm_body(
    const float* __restrict__ A, const float* __restrict__ W,
    float* __restrict__ C, int M,
    const float* __restrict__ G0, const float* __restrict__ G1,
    const int* __restrict__ src, const int* __restrict__ dst)
{
    __shared__ __align__(16) float As[2][BM][APAD];
    __shared__ __align__(16) float Bs[2][BK][BPAD];

    const int tid  = threadIdx.x;
    const int warp = tid >> 5;
    const int lane = tid & 31;
    const int wm   = warp & 3;
    const int wn   = warp >> 2;
    const int bm   = blockIdx.x * BM;
    const int bn   = blockIdx.y * BN;
    const int g    = lane >> 2;
    const int tg   = lane & 3;

    const int ar0 = tid >> 2;
    const int ac  = (tid & 3) * 4;
    const int br0 = tid >> 5;
    const int bc0 = (tid & 31) * 4;

    float acc[2][8][4];
#pragma unroll
    for (int i = 0; i < 2; i++)
#pragma unroll
        for (int j = 0; j < 8; j++)
#pragma unroll
            for (int q = 0; q < 4; q++) acc[i][j][q] = 0.f;

    float4 av[2], bv[2];

    auto gload = [&](int k0) {
        const float4 z = make_float4(0.f, 0.f, 0.f, 0.f);
        int r0 = bm + ar0, r1 = bm + ar0 + 64;
        av[0] = (r0 < M) ? *(const float4*)(A + (size_t)r0 * 256 + k0 + ac) : z;
        av[1] = (r1 < M) ? *(const float4*)(A + (size_t)r1 * 256 + k0 + ac) : z;
        bv[0] = *(const float4*)(W + (size_t)(k0 + br0) * 256 + bn + bc0);
        bv[1] = *(const float4*)(W + (size_t)(k0 + br0 + 8) * 256 + bn + bc0);
    };
    auto sstore = [&](int s) {
        float4 v;
        v = av[0]; v.x = ftf32(v.x); v.y = ftf32(v.y); v.z = ftf32(v.z); v.w = ftf32(v.w);
        *(float4*)(&As[s][ar0][ac]) = v;
        v = av[1]; v.x = ftf32(v.x); v.y = ftf32(v.y); v.z = ftf32(v.z); v.w = ftf32(v.w);
        *(float4*)(&As[s][ar0 + 64][ac]) = v;
        v = bv[0]; v.x = ftf32(v.x); v.y = ftf32(v.y); v.z = ftf32(v.z); v.w = ftf32(v.w);
        *(float4*)(&Bs[s][br0][bc0]) = v;
        v = bv[1]; v.x = ftf32(v.x); v.y = ftf32(v.y); v.z = ftf32(v.z); v.w = ftf32(v.w);
        *(float4*)(&Bs[s][br0 + 8][bc0]) = v;
    };

    gload(0);
    sstore(0);
    __syncthreads();

#pragma unroll 2
    for (int kt = 0; kt < 16; kt++) {
        const int cur = kt & 1;
        if (kt < 15) gload((kt + 1) * BK);

#pragma unroll
        for (int ks = 0; ks < 2; ks++) {
            const int k = ks * 8;
            unsigned af[2][4];
#pragma unroll
            for (int mt = 0; mt < 2; mt++) {
                const int rb = wm * 32 + mt * 16;
                af[mt][0] = __float_as_uint(As[cur][rb + g][k + tg]);
                af[mt][1] = __float_as_uint(As[cur][rb + g + 8][k + tg]);
                af[mt][2] = __float_as_uint(As[cur][rb + g][k + tg + 4]);
                af[mt][3] = __float_as_uint(As[cur][rb + g + 8][k + tg + 4]);
            }
            unsigned bf[8][2];
#pragma unroll
            for (int nt = 0; nt < 8; nt++) {
                const int n = wn * 64 + nt * 8 + g;
                bf[nt][0] = __float_as_uint(Bs[cur][k + tg][n]);
                bf[nt][1] = __float_as_uint(Bs[cur][k + tg + 4][n]);
            }
#pragma unroll
            for (int mt = 0; mt < 2; mt++)
#pragma unroll
                for (int nt = 0; nt < 8; nt++)
                    mma8(acc[mt][nt], af[mt], bf[nt]);
        }

        // single barrier per k-tile: stores go to the buffer nobody reads
        if (kt < 15) sstore((kt + 1) & 1);
        __syncthreads();
    }

#pragma unroll
    for (int mt = 0; mt < 2; mt++) {
#pragma unroll
        for (int rr = 0; rr < 2; rr++) {
            const int r = bm + wm * 32 + mt * 16 + rr * 8 + g;
            if (r < M) {
                int s = 0, d = 0;
                if (EDGE) { s = src[r]; d = dst[r]; }
#pragma unroll
                for (int nt = 0; nt < 8; nt++) {
                    const int col = bn + wn * 64 + nt * 8 + tg * 2;
                    float2 o = make_float2(acc[mt][nt][rr * 2], acc[mt][nt][rr * 2 + 1]);
                    if (EDGE) {
                        float2 gs = *(const float2*)(G0 + (size_t)s * 256 + col);
                        float2 gd = *(const float2*)(G1 + (size_t)d * 256 + col);
                        o.x += gs.x + gd.x;
                        o.y += gs.y + gd.y;
                    }
                    *(float2*)(C + (size_t)r * 256 + col) = o;
                }
            }
        }
    }
}

// batched node GEMM: blockIdx.z selects which of 5 weight/output pairs
struct NodeGemmParams { const float* W[5]; float* C[5]; };

__global__ __launch_bounds__(256)
void tgemm_node(const float* __restrict__ A, NodeGemmParams p, int M) {
    gemm_body<false>(A, p.W[blockIdx.z], p.C[blockIdx.z], M,
                     nullptr, nullptr, nullptr, nullptr);
}

__global__ __launch_bounds__(256)
void tgemm_edge(const float* __restrict__ A, const float* __restrict__ W,
                float* __restrict__ C, int M,
                const float* __restrict__ G0, const float* __restrict__ G1,
                const int* __restrict__ src, const int* __restrict__ dst) {
    gemm_body<true>(A, W, C, M, G0, G1, src, dst);
}

// ---------------- CSR build --------------------------------------------------
__global__ void k_zero_deg(int* __restrict__ df, int* __restrict__ db) {
    int i = blockIdx.x * blockDim.x + threadIdx.x;
    if (i < NNODE) { df[i] = 0; db[i] = 0; }
}
__global__ void k_count(const int* __restrict__ src, const int* __restrict__ dst,
                        int* __restrict__ degf, int* __restrict__ degb) {
    int e = blockIdx.x * blockDim.x + threadIdx.x;
    if (e >= NEDGE) return;
    atomicAdd(&degf[dst[e]], 1);
    atomicAdd(&degb[src[e]], 1);
}
__device__ void scan_one(const int* __restrict__ deg, int* __restrict__ rp,
                         int* __restrict__ cur, int* sm) {
    const int t  = threadIdx.x;
    const int CH = (NNODE + 1023) / 1024;
    int lo = t * CH;
    int hi = lo + CH; if (hi > NNODE) hi = NNODE;
    int s = 0;
    for (int i = lo; i < hi; i++) s += deg[i];
    sm[t] = s;
    __syncthreads();
    for (int off = 1; off < 1024; off <<= 1) {
        int v = (t >= off) ? sm[t - off] : 0;
        __syncthreads();
        sm[t] += v;
        __syncthreads();
    }
    int run = (t == 0) ? 0 : sm[t - 1];
    for (int i = lo; i < hi; i++) { rp[i] = run; cur[i] = run; run += deg[i]; }
    if (t == 1023) rp[NNODE] = run;
    __syncthreads();
}
__global__ void k_scan(const int* degf, const int* degb,
                       int* rpf, int* rpb, int* curf, int* curb) {
    __shared__ int sm[1024];
    scan_one(degf, rpf, curf, sm);
    scan_one(degb, rpb, curb, sm);
}
__global__ void k_fill(const int* __restrict__ src, const int* __restrict__ dst,
                       int* __restrict__ curf, int* __restrict__ curb,
                       int* __restrict__ eidf, int* __restrict__ eidb) {
    int e = blockIdx.x * blockDim.x + threadIdx.x;
    if (e >= NEDGE) return;
    int p = atomicAdd(&curf[dst[e]], 1);
    eidf[p] = e;
    int q = atomicAdd(&curb[src[e]], 1);
    eidb[q] = e;
}

// ---------------- fused edge colstats + attention logits ---------------------
__global__ __launch_bounds__(256)
void k_estats(const float* __restrict__ X,
              const float* __restrict__ af, const float* __restrict__ ab,
              float* __restrict__ lf, float* __restrict__ lb,
              float* __restrict__ sum, float* __restrict__ ssq) {
    __shared__ float s_s[256], s_q[256];
    const int tid = threadIdx.x, lane = tid & 31, warp = tid >> 5;
    s_s[tid] = 0.f; s_q[tid] = 0.f;
    __syncthreads();

    const float4* af4 = (const float4*)af;
    const float4* ab4 = (const float4*)ab;
    const float4 fa0 = af4[lane], fa1 = af4[lane + 32];
    const float4 ba0 = ab4[lane], ba1 = ab4[lane + 32];

    float cs[8] = {0}, cq[8] = {0};

    long w  = (long)blockIdx.x * 8 + warp;
    long nw = (long)gridDim.x * 8;
    for (long r = w; r < NEDGE; r += nw) {
        const float4* row = (const float4*)(X + r * 256);
        float4 v0 = row[lane], v1 = row[lane + 32];
        cs[0] += v0.x; cs[1] += v0.y; cs[2] += v0.z; cs[3] += v0.w;
        cs[4] += v1.x; cs[5] += v1.y; cs[6] += v1.z; cs[7] += v1.w;
        cq[0] += v0.x * v0.x; cq[1] += v0.y * v0.y; cq[2] += v0.z * v0.z; cq[3] += v0.w * v0.w;
        cq[4] += v1.x * v1.x; cq[5] += v1.y * v1.y; cq[6] += v1.z * v1.z; cq[7] += v1.w * v1.w;
        float df = v0.x * fa0.x + v0.y * fa0.y + v0.z * fa0.z + v0.w * fa0.w
                 + v1.x * fa1.x + v1.y * fa1.y + v1.z * fa1.z + v1.w * fa1.w;
        float db = v0.x * ba0.x + v0.y * ba0.y + v0.z * ba0.z + v0.w * ba0.w
                 + v1.x * ba1.x + v1.y * ba1.y + v1.z * ba1.z + v1.w * ba1.w;
#pragma unroll
        for (int o = 16; o > 0; o >>= 1) {
            df += __shfl_xor_sync(0xffffffffu, df, o);
            db += __shfl_xor_sync(0xffffffffu, db, o);
        }
        if (lane == 0) {
            lf[r] = df > 0.f ? df : 0.2f * df;   // leaky relu applied here
            lb[r] = db > 0.f ? db : 0.2f * db;
        }
    }
#pragma unroll
    for (int k = 0; k < 4; k++) {
        atomicAdd(&s_s[lane * 4 + k], cs[k]);
        atomicAdd(&s_s[128 + lane * 4 + k], cs[4 + k]);
        atomicAdd(&s_q[lane * 4 + k], cq[k]);
        atomicAdd(&s_q[128 + lane * 4 + k], cq[4 + k]);
    }
    __syncthreads();
    atomicAdd(&sum[tid], s_s[tid]);
    atomicAdd(&ssq[tid], s_q[tid]);
}

// ---------------- BN stats (node-side) ---------------------------------------
__global__ void k_zero_stats(float* __restrict__ sum, float* __restrict__ ssq) {
    int c = threadIdx.x;
    sum[c] = 0.f;
    ssq[c] = 0.f;
}
__global__ void k_colstats(const float* __restrict__ X, int M,
                           float* __restrict__ sum, float* __restrict__ ssq) {
    int c = threadIdx.x;
    long chunk = ((long)M + gridDim.x - 1) / gridDim.x;
    long r0 = (long)blockIdx.x * chunk;
    long r1 = r0 + chunk;
    if (r1 > M) r1 = M;
    float s = 0.f, q = 0.f;
    for (long r = r0; r < r1; r++) {
        float v = X[r * FDIM + c];
        s += v; q += v * v;
    }
    atomicAdd(&sum[c], s);
    atomicAdd(&ssq[c], q);
}
__global__ void k_bnfin(const float* __restrict__ sum, const float* __restrict__ ssq,
                        int M, float* __restrict__ mean, float* __restrict__ rstd) {
    int c = threadIdx.x;
    float mu  = sum[c] / (float)M;
    float var = ssq[c] / (float)M - mu * mu;
    mean[c] = mu;
    rstd[c] = rsqrtf(var + 1e-5f);
}

// ---------------- residual + BN + relu ---------------------------------------
__global__ void k_bnres(float4* __restrict__ out, const float4* __restrict__ in,
                        const float4* __restrict__ tmp,
                        const float4* __restrict__ mean, const float4* __restrict__ rstd,
                        const float4* __restrict__ gam, const float4* __restrict__ bet,
                        long n4) {
    long i = (long)blockIdx.x * blockDim.x + threadIdx.x;
    if (i >= n4) return;
    int c = (int)(i & 63);
    float4 t = tmp[i], v = in[i];
    float4 m = mean[c], r = rstd[c], g = gam[c], b = bet[c];
    float x;
    x = (t.x - m.x) * r.x * g.x + b.x; v.x += x > 0.f ? x : 0.f;
    x = (t.y - m.y) * r.y * g.y + b.y; v.y += x > 0.f ? x : 0.f;
    x = (t.z - m.z) * r.z * g.z + b.z; v.z += x > 0.f ? x : 0.f;
    x = (t.w - m.w) * r.w * g.w + b.w; v.w += x > 0.f ? x : 0.f;
    out[i] = v;
}

// ---------------- per-node softmax + aggregation (CSR gather, no atomics) ----
__device__ __forceinline__ float bred(float v, float* s, bool ismax) {
    const int lane = threadIdx.x & 31, warp = threadIdx.x >> 5;
#pragma unroll
    for (int o = 16; o > 0; o >>= 1) {
        float t = __shfl_xor_sync(0xffffffffu, v, o);
        v = ismax ? fmaxf(v, t) : v + t;
    }
    if (lane == 0) s[warp] = v;
    __syncthreads();
    if (threadIdx.x == 0) {
        float r = s[0];
#pragma unroll
        for (int i = 1; i < 8; i++) r = ismax ? fmaxf(r, s[i]) : r + s[i];
        s[0] = r;
    }
    __syncthreads();
    float r = s[0];
    __syncthreads();
    return r;
}

#define DEG_CAP 1024

__device__ float agg_one(int n, const int* __restrict__ rp, const int* __restrict__ eid,
                         const int* __restrict__ oth, const float* __restrict__ lg,
                         const float* __restrict__ feat,
                         int* s_i, float* s_a, float* s_red) {
    const int tid = threadIdx.x;
    const int beg = rp[n], end = rp[n + 1];
    const int deg = end - beg;
    if (deg == 0) return 0.f;
    const bool c = (deg <= DEG_CAP);

    float m = -3.4e38f;
    for (int j = tid; j < deg; j += 256) {
        int e = __ldg(&eid[beg + j]);
        float l = __ldg(&lg[e]);
        if (c) { s_i[j] = e; s_a[j] = l; }
        m = fmaxf(m, l);
    }
    m = bred(m, s_red, true);

    float den = 0.f;
    for (int j = tid; j < deg; j += 256) {
        int e = c ? s_i[j] : __ldg(&eid[beg + j]);
        float l = c ? s_a[j] : __ldg(&lg[e]);
        float ex = __expf(l - m);
        int o = __ldg(&oth[e]);
        if (c) { s_a[j] = ex; s_i[j] = o; }
        den += ex;
    }
    den = bred(den, s_red, false);
    const float rden = 1.f / (den + 1e-9f);

    float a0 = 0.f, a1 = 0.f, a2 = 0.f, a3 = 0.f;
    if (c) {
        int j = 0;
        for (; j + 4 <= deg; j += 4) {
            a0 = fmaf(s_a[j + 0], feat[(size_t)s_i[j + 0] * 256 + tid], a0);
            a1 = fmaf(s_a[j + 1], feat[(size_t)s_i[j + 1] * 256 + tid], a1);
            a2 = fmaf(s_a[j + 2], feat[(size_t)s_i[j + 2] * 256 + tid], a2);
            a3 = fmaf(s_a[j + 3], feat[(size_t)s_i[j + 3] * 256 + tid], a3);
        }
        for (; j < deg; j++)
            a0 = fmaf(s_a[j], feat[(size_t)s_i[j] * 256 + tid], a0);
    } else {
        for (int j = 0; j < deg; j++) {
            int e = __ldg(&eid[beg + j]);
            float ex = __expf(__ldg(&lg[e]) - m);
            int o = __ldg(&oth[e]);
            a0 = fmaf(ex, feat[(size_t)o * 256 + tid], a0);
        }
    }
    return ((a0 + a1) + (a2 + a3)) * rden;
}

__global__ __launch_bounds__(256)
void k_node_agg(const int* __restrict__ rpf, const int* __restrict__ eidf,
                const int* __restrict__ src,
                const int* __restrict__ rpb, const int* __restrict__ eidb,
                const int* __restrict__ dst,
                const float* __restrict__ lf, const float* __restrict__ lb,
                const float* __restrict__ hwf, const float* __restrict__ hwb,
                float* __restrict__ htmp) {
    __shared__ int   s_i[DEG_CAP];
    __shared__ float s_a[DEG_CAP];
    __shared__ float s_red[8];
    const int n = blockIdx.x;
    float acc = agg_one(n, rpf, eidf, src, lf, hwf, s_i, s_a, s_red);
    __syncthreads();
    acc += agg_one(n, rpb, eidb, dst, lb, hwb, s_i, s_a, s_red);
    htmp[(size_t)n * 256 + threadIdx.x] += acc;
}

// ---------------- launcher ---------------------------------------------------
extern "C" void kernel_launch(void* const* d_in, const int* in_sizes, int n_in,
                              void* d_out, int out_size) {
    const float* in_h   = (const float*)d_in[0];
    const float* in_e   = (const float*)d_in[1];
    const int*   src    = (const int*)d_in[2];
    const int*   dst    = (const int*)d_in[3];
    const float* We     = (const float*)d_in[4];
    const float* Ws     = (const float*)d_in[5];
    const float* Wd     = (const float*)d_in[6];
    const float* Wself  = (const float*)d_in[7];
    const float* Wf     = (const float*)d_in[8];
    const float* Wb     = (const float*)d_in[9];
    const float* att_f  = (const float*)d_in[10];
    const float* att_b  = (const float*)d_in[11];
    const float* ge     = (const float*)d_in[12];
    const float* be     = (const float*)d_in[13];
    const float* gh     = (const float*)d_in[14];
    const float* bh     = (const float*)d_in[15];

    float* h_out = (float*)d_out;
    float* e_out = (float*)d_out + (size_t)NNODE * FDIM;

    float *etmp, *hw, *logf, *logb, *sum, *ssq, *mean, *rstd;
    int *degf, *degb, *rpf, *rpb, *curf, *curb, *eidf, *eidb;
    cudaGetSymbolAddress((void**)&etmp, g_etmp);
    cudaGetSymbolAddress((void**)&hw,   g_hw);
    cudaGetSymbolAddress((void**)&logf, g_logf);
    cudaGetSymbolAddress((void**)&logb, g_logb);
    cudaGetSymbolAddress((void**)&degf, g_degf);
    cudaGetSymbolAddress((void**)&degb, g_degb);
    cudaGetSymbolAddress((void**)&rpf,  g_rpf);
    cudaGetSymbolAddress((void**)&rpb,  g_rpb);
    cudaGetSymbolAddress((void**)&curf, g_curf);
    cudaGetSymbolAddress((void**)&curb, g_curb);
    cudaGetSymbolAddress((void**)&eidf, g_eidf);
    cudaGetSymbolAddress((void**)&eidb, g_eidb);
    cudaGetSymbolAddress((void**)&sum,  g_sum);
    cudaGetSymbolAddress((void**)&ssq,  g_ssq);
    cudaGetSymbolAddress((void**)&mean, g_mean);
    cudaGetSymbolAddress((void**)&rstd, g_rstd);

    const size_t NF = (size_t)NNODE * FDIM;
    float* hws  = hw + 0 * NF;
    float* hwd  = hw + 1 * NF;
    float* hwf  = hw + 2 * NF;
    float* hwb  = hw + 3 * NF;
    float* htmp = hw + 4 * NF;

    // ---- CSR build (once per launch; graph is static across layers) ----
    k_zero_deg<<<(NNODE + 255) / 256, 256>>>(degf, degb);
    k_count<<<(NEDGE + 255) / 256, 256>>>(src, dst, degf, degb);
    k_scan<<<1, 1024>>>(degf, degb, rpf, rpb, curf, curb);
    k_fill<<<(NEDGE + 255) / 256, 256>>>(src, dst, curf, curb, eidf, eidb);

    dim3 gN((NNODE + BM - 1) / BM, 2, 5);
    dim3 gE(NEDGE / BM, 2);

    for (int l = 0; l < NL; l++) {
        const float* h_in = (l == 0) ? in_h : h_out;
        const float* e_in = (l == 0) ? in_e : e_out;
        size_t WO = (size_t)l * FDIM * FDIM;
        size_t VO = (size_t)l * FDIM;

        NodeGemmParams p;
        p.W[0] = Ws + WO;    p.C[0] = hws;
        p.W[1] = Wd + WO;    p.C[1] = hwd;
        p.W[2] = Wf + WO;    p.C[2] = hwf;
        p.W[3] = Wb + WO;    p.C[3] = hwb;
        p.W[4] = Wself + WO; p.C[4] = htmp;
        tgemm_node<<<gN, 256>>>(h_in, p, NNODE);

        tgemm_edge<<<gE, 256>>>(e_in, We + WO, etmp, NEDGE, hws, hwd, src, dst);

        // fused edge BN stats + attention logits (one pass over etmp)
        k_zero_stats<<<1, 256>>>(sum, ssq);
        k_estats<<<1024, 256>>>(etmp, att_f + VO, att_b + VO, logf, logb, sum, ssq);
        k_bnfin<<<1, 256>>>(sum, ssq, NEDGE, mean, rstd);

        // e_new = e + relu(bn(e_tmp))
        k_bnres<<<(int)(((long)NEDGE * 64 + 255) / 256), 256>>>(
            (float4*)e_out, (const float4*)e_in, (const float4*)etmp,
            (const float4*)mean, (const float4*)rstd,
            (const float4*)(ge + VO), (const float4*)(be + VO), (long)NEDGE * 64);

        // per-node softmax + aggregation (both directions), no atomics
        k_node_agg<<<NNODE, 256>>>(rpf, eidf, src, rpb, eidb, dst,
                                   logf, logb, hwf, hwb, htmp);

        // node BN + residual
        k_zero_stats<<<1, 256>>>(sum, ssq);
        k_colstats<<<256, 256>>>(htmp, NNODE, sum, ssq);
        k_bnfin<<<1, 256>>>(sum, ssq, NNODE, mean, rstd);
        k_bnres<<<(int)(((long)NNODE * 64 + 255) / 256), 256>>>(
            (float4*)h_out, (const float4*)h_in, (const float4*)htmp,
            (const float4*)mean, (const float4*)rstd,
            (const float4*)(gh + VO), (const float4*)(bh + VO), (long)NNODE * 64);
    }
}